// round 1
// baseline (speedup 1.0000x reference)
#include <cuda_runtime.h>
#include <math.h>

#define Bb 16
#define Cc 256
#define Nn 4096
#define Hh 4
#define Dd 64
#define Gg 32
#define CGr 8          // channels per group
#define THREEC 768
#define NSPLIT 8
#define NCHUNK 512     // Nn / NSPLIT

// -------- scratch (no allocations allowed; device globals) --------
__device__ float g_xn[(size_t)Bb * Cc * Nn];          // 67 MB
__device__ float g_qkv[(size_t)Bb * THREEC * Nn];     // 201 MB (q,k already elu+1'd)
__device__ float g_attn[(size_t)Bb * Cc * Nn];        // 67 MB
__device__ float g_kv[(size_t)NSPLIT * Bb * Hh * Dd * Dd];
__device__ float g_ks[(size_t)NSPLIT * Bb * Hh * Dd];

// ============================================================
// K1: GroupNorm. One block per (b, group). group = 8 ch x 4096 = 32768 floats.
// ============================================================
__global__ __launch_bounds__(256) void gn_kernel(const float* __restrict__ x,
                                                 const float* __restrict__ gamma,
                                                 const float* __restrict__ beta) {
    const int b = blockIdx.x >> 5;
    const int g = blockIdx.x & 31;
    const size_t base = ((size_t)b * Cc + (size_t)g * CGr) * Nn;
    const float4* x4 = (const float4*)(x + base);
    float4* o4 = (float4*)(g_xn + base);
    const int t = threadIdx.x;

    float s = 0.f, ss = 0.f;
    const int n4 = CGr * Nn / 4;  // 8192
    #pragma unroll 4
    for (int i = t; i < n4; i += 256) {
        float4 v = x4[i];
        s  += v.x + v.y + v.z + v.w;
        ss += v.x * v.x + v.y * v.y + v.z * v.z + v.w * v.w;
    }
    __shared__ float red[64];
    #pragma unroll
    for (int o = 16; o; o >>= 1) {
        s  += __shfl_xor_sync(0xffffffffu, s, o);
        ss += __shfl_xor_sync(0xffffffffu, ss, o);
    }
    const int w = t >> 5;
    if ((t & 31) == 0) { red[w] = s; red[32 + w] = ss; }
    __syncthreads();
    if (t < 32) {
        s  = (t < 8) ? red[t] : 0.f;
        ss = (t < 8) ? red[32 + t] : 0.f;
        #pragma unroll
        for (int o = 4; o; o >>= 1) {
            s  += __shfl_xor_sync(0xffffffffu, s, o);
            ss += __shfl_xor_sync(0xffffffffu, ss, o);
        }
        if (t == 0) { red[0] = s; red[1] = ss; }
    }
    __syncthreads();
    const float inv = 1.f / (float)(CGr * Nn);
    const float mean = red[0] * inv;
    const float var = red[1] * inv - mean * mean;
    const float rstd = rsqrtf(var + 1e-5f);
    #pragma unroll 4
    for (int i = t; i < n4; i += 256) {
        const int ch = g * CGr + (i >> 10);  // (i*4)/4096
        const float ga = gamma[ch] * rstd;
        const float be = beta[ch] - mean * ga;
        float4 v = x4[i];
        v.x = v.x * ga + be; v.y = v.y * ga + be;
        v.z = v.z * ga + be; v.w = v.w * ga + be;
        o4[i] = v;
    }
}

// ============================================================
// K2 / K5: Y[b,o,n] = sum_c W[o,c] * X[b,c,n] + bias[o] (+ elu / + residual)
// 128x64 tile, BK=16, 256 threads, 8x4 micro-tile.
// MODE 0: X = g_xn, Y = g_qkv, elu(.)+1 applied for o < 512 (q and k)
// MODE 1: X = g_attn, Y = d_out, += resid (original x)
// ============================================================
template <int MODE>
__global__ __launch_bounds__(256) void gemm_kernel(const float* __restrict__ W,
                                                   const float* __restrict__ bias,
                                                   const float* __restrict__ resid,
                                                   float* __restrict__ Yout) {
    const int b = blockIdx.z;
    const int n0 = blockIdx.x * 64;
    const int o0 = blockIdx.y * 128;
    const float* X = (MODE == 0 ? g_xn : g_attn) + (size_t)b * Cc * Nn;

    __shared__ __align__(16) float Ws[16][132];  // [kk][oo], padded (132 ≡ 4 mod 32)
    __shared__ __align__(16) float Xs[16][64];   // [kk][nn]

    const int t = threadIdx.x;
    const int tx = t & 15;       // 0..15 -> n micro (4 cols)
    const int ty = t >> 4;       // 0..15 -> o micro (8 rows)
    const int wk4 = t & 3;       // W loader: float4 along c
    const int woo = t >> 2;      // 0..63 (two passes -> 128 rows)
    const int xk  = t >> 6;      // X loader row base
    const int xn  = t & 63;

    float acc[8][4];
    #pragma unroll
    for (int i = 0; i < 8; i++)
        #pragma unroll
        for (int j = 0; j < 4; j++) acc[i][j] = 0.f;

    for (int kt = 0; kt < Cc; kt += 16) {
        #pragma unroll
        for (int p = 0; p < 2; p++) {
            const int oo = woo + p * 64;
            const float4 wv = *(const float4*)(W + (size_t)(o0 + oo) * Cc + kt + wk4 * 4);
            Ws[wk4 * 4 + 0][oo] = wv.x;
            Ws[wk4 * 4 + 1][oo] = wv.y;
            Ws[wk4 * 4 + 2][oo] = wv.z;
            Ws[wk4 * 4 + 3][oo] = wv.w;
        }
        #pragma unroll
        for (int p = 0; p < 4; p++) {
            const int kk = xk + p * 4;
            Xs[kk][xn] = X[(size_t)(kt + kk) * Nn + n0 + xn];
        }
        __syncthreads();
        #pragma unroll
        for (int kk = 0; kk < 16; kk++) {
            const float4 a0 = *(const float4*)&Ws[kk][ty * 8];
            const float4 a1 = *(const float4*)&Ws[kk][ty * 8 + 4];
            const float4 bx = *(const float4*)&Xs[kk][tx * 4];
            const float av[8] = {a0.x, a0.y, a0.z, a0.w, a1.x, a1.y, a1.z, a1.w};
            const float bv[4] = {bx.x, bx.y, bx.z, bx.w};
            #pragma unroll
            for (int i = 0; i < 8; i++)
                #pragma unroll
                for (int j = 0; j < 4; j++) acc[i][j] += av[i] * bv[j];
        }
        __syncthreads();
    }

    #pragma unroll
    for (int i = 0; i < 8; i++) {
        const int o = o0 + ty * 8 + i;
        const float bs = bias[o];
        float4 v;
        v.x = acc[i][0] + bs; v.y = acc[i][1] + bs;
        v.z = acc[i][2] + bs; v.w = acc[i][3] + bs;
        if (MODE == 0) {
            if (o < 2 * Cc) {  // q,k: elu(x)+1 = x+1 (x>0) else exp(x)
                v.x = v.x > 0.f ? v.x + 1.f : expf(v.x);
                v.y = v.y > 0.f ? v.y + 1.f : expf(v.y);
                v.z = v.z > 0.f ? v.z + 1.f : expf(v.z);
                v.w = v.w > 0.f ? v.w + 1.f : expf(v.w);
            }
            *(float4*)(g_qkv + ((size_t)b * THREEC + o) * Nn + n0 + tx * 4) = v;
        } else {
            const float4 r = *(const float4*)(resid + ((size_t)b * Cc + o) * Nn + n0 + tx * 4);
            v.x += r.x; v.y += r.y; v.z += r.z; v.w += r.w;
            *(float4*)(Yout + ((size_t)b * Cc + o) * Nn + n0 + tx * 4) = v;
        }
    }
}

// ============================================================
// K3: per (b,h,split): kv[d,e] += sum_n k[d,n]*v[e,n]; ks[d] += sum_n k[d,n]
// 64x64 output, n tiled by 16, deterministic split partials.
// ============================================================
__global__ __launch_bounds__(256) void kv_kernel() {
    const int bh = blockIdx.x;     // 0..63
    const int split = blockIdx.y;  // 0..7
    const int b = bh >> 2, h = bh & 3;
    const float* Kp = g_qkv + ((size_t)b * THREEC + Cc + h * Dd) * Nn;
    const float* Vp = g_qkv + ((size_t)b * THREEC + 2 * Cc + h * Dd) * Nn;

    __shared__ __align__(16) float Ks[16][68];  // [nl][d]
    __shared__ __align__(16) float Vs[16][68];  // [nl][e]

    const int t = threadIdx.x;
    const int tx = t & 15, ty = t >> 4;
    const int ld = t >> 2;   // 0..63
    const int ln4 = t & 3;   // float4 group along n

    float acc[4][4];
    #pragma unroll
    for (int i = 0; i < 4; i++)
        #pragma unroll
        for (int j = 0; j < 4; j++) acc[i][j] = 0.f;
    float ksacc = 0.f;

    const int nbase = split * NCHUNK;
    for (int nt = 0; nt < NCHUNK; nt += 16) {
        const int n0g = nbase + nt;
        const float4 k4 = *(const float4*)(Kp + (size_t)ld * Nn + n0g + ln4 * 4);
        const float4 v4 = *(const float4*)(Vp + (size_t)ld * Nn + n0g + ln4 * 4);
        Ks[ln4 * 4 + 0][ld] = k4.x; Ks[ln4 * 4 + 1][ld] = k4.y;
        Ks[ln4 * 4 + 2][ld] = k4.z; Ks[ln4 * 4 + 3][ld] = k4.w;
        Vs[ln4 * 4 + 0][ld] = v4.x; Vs[ln4 * 4 + 1][ld] = v4.y;
        Vs[ln4 * 4 + 2][ld] = v4.z; Vs[ln4 * 4 + 3][ld] = v4.w;
        __syncthreads();
        #pragma unroll
        for (int nl = 0; nl < 16; nl++) {
            const float4 a = *(const float4*)&Ks[nl][ty * 4];
            const float4 bb = *(const float4*)&Vs[nl][tx * 4];
            const float av[4] = {a.x, a.y, a.z, a.w};
            const float bv[4] = {bb.x, bb.y, bb.z, bb.w};
            #pragma unroll
            for (int i = 0; i < 4; i++)
                #pragma unroll
                for (int j = 0; j < 4; j++) acc[i][j] += av[i] * bv[j];
        }
        if (t < 64) {
            #pragma unroll
            for (int nl = 0; nl < 16; nl++) ksacc += Ks[nl][t];
        }
        __syncthreads();
    }

    float* kvout = g_kv + ((size_t)split * 64 + bh) * Dd * Dd;
    #pragma unroll
    for (int i = 0; i < 4; i++) {
        float4 v;
        v.x = acc[i][0]; v.y = acc[i][1]; v.z = acc[i][2]; v.w = acc[i][3];
        *(float4*)(kvout + (size_t)(ty * 4 + i) * Dd + tx * 4) = v;
    }
    if (t < 64) g_ks[((size_t)split * 64 + bh) * Dd + t] = ksacc;
}

// ============================================================
// K4: reduce kv partials; out[e,n] = (sum_d kv[d,e] q[d,n]) / (q·ksum + eps)
// one thread per n column; kv broadcast from smem.
// ============================================================
__global__ __launch_bounds__(256) void attn_kernel() {
    const int bh = blockIdx.x;  // 0..63
    const int nc = blockIdx.y;  // 0..15
    const int b = bh >> 2, h = bh & 3;

    __shared__ __align__(16) float kvs[64 * 64];
    __shared__ float kss[64];

    const int t = threadIdx.x;
    for (int i = t; i < 4096; i += 256) {
        float s = 0.f;
        #pragma unroll
        for (int sp = 0; sp < NSPLIT; sp++)
            s += g_kv[((size_t)sp * 64 + bh) * 4096 + i];
        kvs[i] = s;
    }
    if (t < 64) {
        float s = 0.f;
        #pragma unroll
        for (int sp = 0; sp < NSPLIT; sp++)
            s += g_ks[((size_t)sp * 64 + bh) * 64 + t];
        kss[t] = s;
    }
    __syncthreads();

    const int n = nc * 256 + t;
    const float* Qp = g_qkv + ((size_t)b * THREEC + h * Dd) * Nn + n;
    float out[64];
    #pragma unroll
    for (int e = 0; e < 64; e++) out[e] = 0.f;
    float denom = 0.f;

    for (int d = 0; d < 64; d++) {
        const float qd = Qp[(size_t)d * Nn];
        denom += qd * kss[d];
        const float4* row = (const float4*)&kvs[d * 64];
        #pragma unroll
        for (int e4 = 0; e4 < 16; e4++) {
            const float4 kv4 = row[e4];
            out[e4 * 4 + 0] += kv4.x * qd;
            out[e4 * 4 + 1] += kv4.y * qd;
            out[e4 * 4 + 2] += kv4.z * qd;
            out[e4 * 4 + 3] += kv4.w * qd;
        }
    }
    const float sc = 1.f / (denom + 1e-6f);
    float* Op = g_attn + ((size_t)b * Cc + h * Dd) * Nn + n;
    #pragma unroll
    for (int e = 0; e < 64; e++) Op[(size_t)e * Nn] = out[e] * sc;
}

// ============================================================
extern "C" void kernel_launch(void* const* d_in, const int* in_sizes, int n_in,
                              void* d_out, int out_size) {
    const float* x     = (const float*)d_in[0];
    const float* gamma = (const float*)d_in[1];
    const float* beta  = (const float*)d_in[2];
    const float* w_qkv = (const float*)d_in[3];
    const float* b_qkv = (const float*)d_in[4];
    const float* w_out = (const float*)d_in[5];
    const float* b_out = (const float*)d_in[6];
    float* out = (float*)d_out;

    gn_kernel<<<Bb * Gg, 256>>>(x, gamma, beta);

    dim3 g2(Nn / 64, THREEC / 128, Bb);
    gemm_kernel<0><<<g2, 256>>>(w_qkv, b_qkv, nullptr, nullptr);

    dim3 g3(Bb * Hh, NSPLIT);
    kv_kernel<<<g3, 256>>>();

    dim3 g4(Bb * Hh, Nn / 256);
    attn_kernel<<<g4, 256>>>();

    dim3 g5(Nn / 64, Cc / 128, Bb);
    gemm_kernel<1><<<g5, 256>>>(w_out, b_out, x, out);
}

// round 5
// speedup vs baseline: 1.4431x; 1.4431x over previous
#include <cuda_runtime.h>
#include <math.h>
#include <stdint.h>

#define Bb 16
#define Cc 256
#define Nn 4096
#define Hh 4
#define THREEC 768
#define NSPLIT 8
#define NCHUNK 512

// -------- scratch (device globals; no allocs allowed) --------
__device__ float g_xnt[(size_t)Bb * Nn * Cc];     // GN output, [b][n][c]
__device__ float g_qkv[(size_t)Bb * THREEC * Nn]; // [b][o][n], q/k already elu+1
__device__ float g_attnt[(size_t)Bb * Nn * Cc];   // attn output, [b][n][c]
__device__ float g_kv[(size_t)NSPLIT * 64 * 64 * 64];
__device__ float g_ks[(size_t)NSPLIT * 64 * 64];

__device__ __forceinline__ float to_tf32(float x) {
    uint32_t u;
    asm("cvt.rna.tf32.f32 %0, %1;" : "=r"(u) : "f"(x));
    return __uint_as_float(u);
}

__device__ __forceinline__ void mma_tf32(float c[4], uint32_t a0, uint32_t a1,
                                         uint32_t a2, uint32_t a3,
                                         uint32_t b0, uint32_t b1) {
    asm volatile(
        "mma.sync.aligned.m16n8k8.row.col.f32.tf32.tf32.f32 "
        "{%0,%1,%2,%3}, {%4,%5,%6,%7}, {%8,%9}, {%0,%1,%2,%3};"
        : "+f"(c[0]), "+f"(c[1]), "+f"(c[2]), "+f"(c[3])
        : "r"(a0), "r"(a1), "r"(a2), "r"(a3), "r"(b0), "r"(b1));
}

// ============================================================
// K1: GroupNorm, writes transposed g_xnt[b][n][c]
// ============================================================
__global__ __launch_bounds__(256) void gn_kernel(const float* __restrict__ x,
                                                 const float* __restrict__ gamma,
                                                 const float* __restrict__ beta) {
    const int b = blockIdx.x >> 5;
    const int g = blockIdx.x & 31;
    const int c0 = g * 8;
    const size_t base = ((size_t)b * Cc + c0) * Nn;
    const float4* x4 = (const float4*)(x + base);
    const int t = threadIdx.x;

    float s = 0.f, ss = 0.f;
    const int n4 = 8 * Nn / 4;
    #pragma unroll 4
    for (int i = t; i < n4; i += 256) {
        float4 v = x4[i];
        s  += v.x + v.y + v.z + v.w;
        ss += v.x * v.x + v.y * v.y + v.z * v.z + v.w * v.w;
    }
    __shared__ float red[64];
    #pragma unroll
    for (int o = 16; o; o >>= 1) {
        s  += __shfl_xor_sync(0xffffffffu, s, o);
        ss += __shfl_xor_sync(0xffffffffu, ss, o);
    }
    const int w = t >> 5;
    if ((t & 31) == 0) { red[w] = s; red[32 + w] = ss; }
    __syncthreads();
    if (t < 32) {
        s  = (t < 8) ? red[t] : 0.f;
        ss = (t < 8) ? red[32 + t] : 0.f;
        #pragma unroll
        for (int o = 4; o; o >>= 1) {
            s  += __shfl_xor_sync(0xffffffffu, s, o);
            ss += __shfl_xor_sync(0xffffffffu, ss, o);
        }
        if (t == 0) { red[0] = s; red[1] = ss; }
    }
    __syncthreads();
    const float inv = 1.f / (float)(8 * Nn);
    const float mean = red[0] * inv;
    const float var = red[1] * inv - mean * mean;
    const float rstd = rsqrtf(var + 1e-5f);

    float ga[8], be[8];
    #pragma unroll
    for (int j = 0; j < 8; j++) {
        ga[j] = gamma[c0 + j] * rstd;
        be[j] = beta[c0 + j] - mean * ga[j];
    }
    const float* xg = x + base;
    float* dst0 = g_xnt + (size_t)b * Nn * Cc + c0;
    for (int i = t; i < Nn; i += 256) {
        float v[8];
        #pragma unroll
        for (int j = 0; j < 8; j++)
            v[j] = __ldg(xg + (size_t)j * Nn + i) * ga[j] + be[j];
        float4* d = (float4*)(dst0 + (size_t)i * Cc);
        d[0] = make_float4(v[0], v[1], v[2], v[3]);
        d[1] = make_float4(v[4], v[5], v[6], v[7]);
    }
}

// ============================================================
// K2/K5: tf32 mma.sync GEMM. D[n,o] = sum_c A[n,c] * W[o,c]
// CTA tile 128(n) x 128(o), BK=32. 8 warps: wm in {0,1} (64 rows),
// wn in {0..3} (32 cols); warp tile 64x32 via 4x4 m16n8k8 frags.
// MODE 0: A=g_xnt -> g_qkv[b][o][n], bias + elu for o<512
// MODE 1: A=g_attnt -> Yout[b][o][n], bias + residual
// ============================================================
#define ASTRIDE 36
#define CSTRIDE 129

template <int MODE>
__global__ __launch_bounds__(256) void mma_gemm(const float* __restrict__ W,
                                                const float* __restrict__ bias,
                                                const float* __restrict__ resid,
                                                float* __restrict__ Yout) {
    __shared__ __align__(16) float sm[2 * 128 * ASTRIDE];  // As | Ws ; Cs overlays
    float* const As = sm;
    float* const Ws = sm + 128 * ASTRIDE;
    float* const Cs = sm;  // [64][CSTRIDE] epilogue overlay

    const int b = blockIdx.z;
    const int n0 = blockIdx.x * 128;
    const int o0 = blockIdx.y * 128;
    const float* Ag = (MODE == 0 ? g_xnt : g_attnt) + (size_t)b * Nn * Cc;

    const int t = threadIdx.x;
    const int l = t & 31;
    const int wid = t >> 5;
    const int wm = wid & 1;
    const int wn = wid >> 1;

    float c[4][4][4];
    #pragma unroll
    for (int i = 0; i < 4; i++)
        #pragma unroll
        for (int j = 0; j < 4; j++)
            #pragma unroll
            for (int r = 0; r < 4; r++) c[i][j][r] = 0.f;

    const int lc4 = t & 7;   // float4 index along k
    const int lr  = t >> 3;  // row 0..31 (4 passes -> 128)

    for (int kt = 0; kt < Cc; kt += 32) {
        #pragma unroll
        for (int p = 0; p < 4; p++) {
            const int r = lr + p * 32;
            float4 av = *(const float4*)(Ag + (size_t)(n0 + r) * Cc + kt + lc4 * 4);
            float4 wv = *(const float4*)(W  + (size_t)(o0 + r) * Cc + kt + lc4 * 4);
            av.x = to_tf32(av.x); av.y = to_tf32(av.y);
            av.z = to_tf32(av.z); av.w = to_tf32(av.w);
            wv.x = to_tf32(wv.x); wv.y = to_tf32(wv.y);
            wv.z = to_tf32(wv.z); wv.w = to_tf32(wv.w);
            *(float4*)(As + r * ASTRIDE + lc4 * 4) = av;
            *(float4*)(Ws + r * ASTRIDE + lc4 * 4) = wv;
        }
        __syncthreads();
        const uint32_t* Asu = (const uint32_t*)As;
        const uint32_t* Wsu = (const uint32_t*)Ws;
        #pragma unroll
        for (int ks = 0; ks < 4; ks++) {
            const int k = ks * 8;
            const int ar = wm * 64 + (l >> 2);
            const int ac = k + (l & 3);
            uint32_t a[4][4];
            #pragma unroll
            for (int mf = 0; mf < 4; mf++) {
                const int r0 = (ar + mf * 16) * ASTRIDE;
                a[mf][0] = Asu[r0 + ac];
                a[mf][1] = Asu[r0 + 8 * ASTRIDE + ac];
                a[mf][2] = Asu[r0 + ac + 4];
                a[mf][3] = Asu[r0 + 8 * ASTRIDE + ac + 4];
            }
            uint32_t bf[4][2];
            const int bn = wn * 32 + (l >> 2);
            #pragma unroll
            for (int nf = 0; nf < 4; nf++) {
                const int r0 = (bn + nf * 8) * ASTRIDE;
                bf[nf][0] = Wsu[r0 + k + (l & 3)];
                bf[nf][1] = Wsu[r0 + k + (l & 3) + 4];
            }
            #pragma unroll
            for (int mf = 0; mf < 4; mf++)
                #pragma unroll
                for (int nf = 0; nf < 4; nf++)
                    mma_tf32(c[mf][nf], a[mf][0], a[mf][1], a[mf][2], a[mf][3],
                             bf[nf][0], bf[nf][1]);
        }
        __syncthreads();
    }

    // ---- epilogue: two m-halves through smem transpose ----
    #pragma unroll
    for (int half = 0; half < 2; half++) {
        if (wm == half) {
            #pragma unroll
            for (int mf = 0; mf < 4; mf++) {
                const int row = mf * 16 + (l >> 2);
                #pragma unroll
                for (int nf = 0; nf < 4; nf++) {
                    const int col = wn * 32 + nf * 8 + (l & 3) * 2;
                    Cs[row * CSTRIDE + col]           = c[mf][nf][0];
                    Cs[row * CSTRIDE + col + 1]       = c[mf][nf][1];
                    Cs[(row + 8) * CSTRIDE + col]     = c[mf][nf][2];
                    Cs[(row + 8) * CSTRIDE + col + 1] = c[mf][nf][3];
                }
            }
        }
        __syncthreads();
        const int nl = t & 63;
        const int ol0 = t >> 6;
        const int n = n0 + half * 64 + nl;
        #pragma unroll
        for (int j = 0; j < 32; j++) {
            const int o = ol0 + j * 4;
            const int og = o0 + o;
            float v = Cs[nl * CSTRIDE + o] + __ldg(bias + og);
            if (MODE == 0) {
                if (og < 2 * Cc) v = v > 0.f ? v + 1.f : expf(v);
                g_qkv[((size_t)b * THREEC + og) * Nn + n] = v;
            } else {
                v += __ldg(resid + ((size_t)b * Cc + og) * Nn + n);
                Yout[((size_t)b * Cc + og) * Nn + n] = v;
            }
        }
        __syncthreads();
    }
}

// ============================================================
// K3: kv[d,e] partials per (b,h,split) + k row sums (fp32)
// ============================================================
__global__ __launch_bounds__(256) void kv_kernel() {
    const int bh = blockIdx.x;
    const int split = blockIdx.y;
    const int b = bh >> 2, h = bh & 3;
    const float* Kp = g_qkv + ((size_t)b * THREEC + Cc + h * 64) * Nn;
    const float* Vp = g_qkv + ((size_t)b * THREEC + 2 * Cc + h * 64) * Nn;

    __shared__ __align__(16) float Ks[16][68];
    __shared__ __align__(16) float Vs[16][68];

    const int t = threadIdx.x;
    const int tx = t & 15, ty = t >> 4;
    const int ld = t >> 2;
    const int ln4 = t & 3;

    float acc[4][4];
    #pragma unroll
    for (int i = 0; i < 4; i++)
        #pragma unroll
        for (int j = 0; j < 4; j++) acc[i][j] = 0.f;
    float ksacc = 0.f;

    const int nbase = split * NCHUNK;
    for (int nt = 0; nt < NCHUNK; nt += 16) {
        const int n0g = nbase + nt;
        const float4 k4 = *(const float4*)(Kp + (size_t)ld * Nn + n0g + ln4 * 4);
        const float4 v4 = *(const float4*)(Vp + (size_t)ld * Nn + n0g + ln4 * 4);
        Ks[ln4 * 4 + 0][ld] = k4.x; Ks[ln4 * 4 + 1][ld] = k4.y;
        Ks[ln4 * 4 + 2][ld] = k4.z; Ks[ln4 * 4 + 3][ld] = k4.w;
        Vs[ln4 * 4 + 0][ld] = v4.x; Vs[ln4 * 4 + 1][ld] = v4.y;
        Vs[ln4 * 4 + 2][ld] = v4.z; Vs[ln4 * 4 + 3][ld] = v4.w;
        __syncthreads();
        #pragma unroll
        for (int nl = 0; nl < 16; nl++) {
            const float4 a = *(const float4*)&Ks[nl][ty * 4];
            const float4 bb = *(const float4*)&Vs[nl][tx * 4];
            const float av[4] = {a.x, a.y, a.z, a.w};
            const float bv[4] = {bb.x, bb.y, bb.z, bb.w};
            #pragma unroll
            for (int i = 0; i < 4; i++)
                #pragma unroll
                for (int j = 0; j < 4; j++) acc[i][j] += av[i] * bv[j];
        }
        if (t < 64) {
            #pragma unroll
            for (int nl = 0; nl < 16; nl++) ksacc += Ks[nl][t];
        }
        __syncthreads();
    }

    float* kvout = g_kv + ((size_t)split * 64 + bh) * 4096;
    #pragma unroll
    for (int i = 0; i < 4; i++) {
        float4 v;
        v.x = acc[i][0]; v.y = acc[i][1]; v.z = acc[i][2]; v.w = acc[i][3];
        *(float4*)(kvout + (size_t)(ty * 4 + i) * 64 + tx * 4) = v;
    }
    if (t < 64) g_ks[((size_t)split * 64 + bh) * 64 + t] = ksacc;
}

// ============================================================
// K3b: reduce kv/ks splits into split-0 slot
// ============================================================
__global__ __launch_bounds__(256) void kvreduce_kernel() {
    const int bh = blockIdx.x;
    const int t = threadIdx.x;
    for (int i = t; i < 4096; i += 256) {
        float s = 0.f;
        #pragma unroll
        for (int sp = 0; sp < NSPLIT; sp++)
            s += g_kv[((size_t)sp * 64 + bh) * 4096 + i];
        g_kv[(size_t)bh * 4096 + i] = s;
    }
    if (t < 64) {
        float s = 0.f;
        #pragma unroll
        for (int sp = 0; sp < NSPLIT; sp++)
            s += g_ks[((size_t)sp * 64 + bh) * 64 + t];
        g_ks[(size_t)bh * 64 + t] = s;
    }
}

// ============================================================
// K4: out[e,n] = (sum_d kv[d,e] q[d,n]) / (q·ksum + eps); writes [b][n][c]
// ============================================================
__global__ __launch_bounds__(256) void attn_kernel() {
    const int bh = blockIdx.x;
    const int b = bh >> 2, h = bh & 3;

    __shared__ __align__(16) float kvs[4096];
    __shared__ float kss[64];

    const int t = threadIdx.x;
    for (int i = t; i < 4096; i += 256) kvs[i] = g_kv[(size_t)bh * 4096 + i];
    if (t < 64) kss[t] = g_ks[(size_t)bh * 64 + t];
    __syncthreads();

    const int nl = t & 127;
    const int eh = t >> 7;
    const int n = blockIdx.y * 128 + nl;
    const float* Qp = g_qkv + ((size_t)b * THREEC + h * 64) * Nn + n;

    float out[32];
    #pragma unroll
    for (int e = 0; e < 32; e++) out[e] = 0.f;
    float denom = 0.f;

    #pragma unroll 4
    for (int d = 0; d < 64; d++) {
        const float qd = __ldg(Qp + (size_t)d * Nn);
        denom += qd * kss[d];
        const float4* row = (const float4*)&kvs[d * 64 + eh * 32];
        #pragma unroll
        for (int e4 = 0; e4 < 8; e4++) {
            const float4 kv4 = row[e4];
            out[e4 * 4 + 0] += kv4.x * qd;
            out[e4 * 4 + 1] += kv4.y * qd;
            out[e4 * 4 + 2] += kv4.z * qd;
            out[e4 * 4 + 3] += kv4.w * qd;
        }
    }
    const float sc = 1.f / (denom + 1e-6f);
    float* Op = g_attnt + ((size_t)b * Nn + n) * Cc + h * 64 + eh * 32;
    #pragma unroll
    for (int e4 = 0; e4 < 8; e4++) {
        float4 v;
        v.x = out[e4 * 4 + 0] * sc; v.y = out[e4 * 4 + 1] * sc;
        v.z = out[e4 * 4 + 2] * sc; v.w = out[e4 * 4 + 3] * sc;
        *(float4*)(Op + e4 * 4) = v;
    }
}

// ============================================================
extern "C" void kernel_launch(void* const* d_in, const int* in_sizes, int n_in,
                              void* d_out, int out_size) {
    const float* x     = (const float*)d_in[0];
    const float* gamma = (const float*)d_in[1];
    const float* beta  = (const float*)d_in[2];
    const float* w_qkv = (const float*)d_in[3];
    const float* b_qkv = (const float*)d_in[4];
    const float* w_out = (const float*)d_in[5];
    const float* b_out = (const float*)d_in[6];
    float* out = (float*)d_out;

    gn_kernel<<<Bb * 32, 256>>>(x, gamma, beta);

    dim3 g2(Nn / 128, THREEC / 128, Bb);
    mma_gemm<0><<<g2, 256>>>(w_qkv, b_qkv, nullptr, nullptr);

    dim3 g3(Bb * Hh, NSPLIT);
    kv_kernel<<<g3, 256>>>();

    kvreduce_kernel<<<Bb * Hh, 256>>>();

    dim3 g4(Bb * Hh, Nn / 128);
    attn_kernel<<<g4, 256>>>();

    dim3 g5(Nn / 128, Cc / 128, Bb);
    mma_gemm<1><<<g5, 256>>>(w_out, b_out, x, out);
}

// round 6
// speedup vs baseline: 1.9916x; 1.3801x over previous
#include <cuda_runtime.h>
#include <math.h>
#include <stdint.h>

#define Bb 16
#define Cc 256
#define Nn 4096
#define Hh 4
#define THREEC 768
#define NSPLIT 4

// -------- scratch (device globals; no allocs allowed) --------
__device__ float g_xnt[(size_t)Bb * Nn * Cc];     // GN output, [b][n][c]
__device__ float g_qkv[(size_t)Bb * THREEC * Nn]; // [b][o][n]; only k,v slots used
__device__ float g_qt[(size_t)Bb * Nn * Cc];      // q, [b][n][h*64+d], elu+1 applied
__device__ float g_attnt[(size_t)Bb * Nn * Cc];   // attn output, [b][n][c]
__device__ float g_kv[(size_t)NSPLIT * 64 * 64 * 64];  // kvT partials [e][d]
__device__ float g_ks[(size_t)NSPLIT * 64 * 64];

__device__ __forceinline__ uint32_t smem_u32(const void* p) {
    uint32_t a;
    asm("{ .reg .u64 t; cvta.to.shared.u64 t, %1; cvt.u32.u64 %0, t; }" : "=r"(a) : "l"(p));
    return a;
}

#define CP16(saddr, gptr) \
    asm volatile("cp.async.cg.shared.global [%0], [%1], 16;" :: "r"(saddr), "l"(gptr))
#define CP_COMMIT() asm volatile("cp.async.commit_group;" ::: "memory")
#define CP_WAIT0()  asm volatile("cp.async.wait_group 0;" ::: "memory")
#define CP_WAIT1()  asm volatile("cp.async.wait_group 1;" ::: "memory")

__device__ __forceinline__ void mma_tf32(float c[4], uint32_t a0, uint32_t a1,
                                         uint32_t a2, uint32_t a3,
                                         uint32_t b0, uint32_t b1) {
    asm volatile(
        "mma.sync.aligned.m16n8k8.row.col.f32.tf32.tf32.f32 "
        "{%0,%1,%2,%3}, {%4,%5,%6,%7}, {%8,%9}, {%0,%1,%2,%3};"
        : "+f"(c[0]), "+f"(c[1]), "+f"(c[2]), "+f"(c[3])
        : "r"(a0), "r"(a1), "r"(a2), "r"(a3), "r"(b0), "r"(b1));
}

// ============================================================
// K1: GroupNorm, writes transposed g_xnt[b][n][c]
// ============================================================
__global__ __launch_bounds__(256) void gn_kernel(const float* __restrict__ x,
                                                 const float* __restrict__ gamma,
                                                 const float* __restrict__ beta) {
    const int b = blockIdx.x >> 5;
    const int g = blockIdx.x & 31;
    const int c0 = g * 8;
    const size_t base = ((size_t)b * Cc + c0) * Nn;
    const float4* x4 = (const float4*)(x + base);
    const int t = threadIdx.x;

    float s = 0.f, ss = 0.f;
    const int n4 = 8 * Nn / 4;
    #pragma unroll 4
    for (int i = t; i < n4; i += 256) {
        float4 v = x4[i];
        s  += v.x + v.y + v.z + v.w;
        ss += v.x * v.x + v.y * v.y + v.z * v.z + v.w * v.w;
    }
    __shared__ float red[64];
    #pragma unroll
    for (int o = 16; o; o >>= 1) {
        s  += __shfl_xor_sync(0xffffffffu, s, o);
        ss += __shfl_xor_sync(0xffffffffu, ss, o);
    }
    const int w = t >> 5;
    if ((t & 31) == 0) { red[w] = s; red[32 + w] = ss; }
    __syncthreads();
    if (t < 32) {
        s  = (t < 8) ? red[t] : 0.f;
        ss = (t < 8) ? red[32 + t] : 0.f;
        #pragma unroll
        for (int o = 4; o; o >>= 1) {
            s  += __shfl_xor_sync(0xffffffffu, s, o);
            ss += __shfl_xor_sync(0xffffffffu, ss, o);
        }
        if (t == 0) { red[0] = s; red[1] = ss; }
    }
    __syncthreads();
    const float inv = 1.f / (float)(8 * Nn);
    const float mean = red[0] * inv;
    const float var = red[1] * inv - mean * mean;
    const float rstd = rsqrtf(var + 1e-5f);

    float ga[8], be[8];
    #pragma unroll
    for (int j = 0; j < 8; j++) {
        ga[j] = gamma[c0 + j] * rstd;
        be[j] = beta[c0 + j] - mean * ga[j];
    }
    const float* xg = x + base;
    float* dst0 = g_xnt + (size_t)b * Nn * Cc + c0;
    for (int i = t; i < Nn; i += 256) {
        float v[8];
        #pragma unroll
        for (int j = 0; j < 8; j++)
            v[j] = __ldg(xg + (size_t)j * Nn + i) * ga[j] + be[j];
        float4* d = (float4*)(dst0 + (size_t)i * Cc);
        d[0] = make_float4(v[0], v[1], v[2], v[3]);
        d[1] = make_float4(v[4], v[5], v[6], v[7]);
    }
}

// ============================================================
// K2/K5: tf32 mma GEMM, cp.async double-buffered.
// D[n,o] = sum_c A[n,c] * W[o,c]; CTA 128x128, BK=32.
// MODE 0: A=g_xnt. q blocks (o0<256): direct frag store -> g_qt[b][n][o], elu.
//         k,v blocks: transpose -> g_qkv[b][o][n], elu for o<512 (k only).
// MODE 1: A=g_attnt -> Yout[b][o][n], bias + residual.
// Dynamic smem: 2 stages x (A 128x36 + W 128x36) floats = 73728 B.
// ============================================================
#define ASTRIDE 36
#define CSTRIDE 129
#define STAGEF 9216   // floats per stage (2 * 128 * 36)

template <int MODE>
__global__ __launch_bounds__(256) void mma_gemm(const float* __restrict__ W,
                                                const float* __restrict__ bias,
                                                const float* __restrict__ resid,
                                                float* __restrict__ Yout) {
    extern __shared__ __align__(16) float dsm[];
    const int b = blockIdx.z;
    const int n0 = blockIdx.x * 128;
    const int o0 = blockIdx.y * 128;
    const float* Ag = (MODE == 0 ? g_xnt : g_attnt) + (size_t)b * Nn * Cc;

    const int t = threadIdx.x;
    const int l = t & 31;
    const int wid = t >> 5;
    const int wm = wid & 1;
    const int wn = wid >> 1;
    const int lc4 = t & 7;
    const int lr  = t >> 3;
    const uint32_t sb = smem_u32(dsm);

    float c[4][4][4] = {};

    auto prefetch = [&](int kt8, int stg) {
        const int kt = kt8 * 32;
        const uint32_t abase = sb + (uint32_t)stg * STAGEF * 4;
        const uint32_t wbase = abase + 4608 * 4;
        #pragma unroll
        for (int p = 0; p < 4; p++) {
            const int r = lr + p * 32;
            const uint32_t off = (uint32_t)(r * ASTRIDE + lc4 * 4) * 4;
            CP16(abase + off, Ag + (size_t)(n0 + r) * Cc + kt + lc4 * 4);
            CP16(wbase + off, W  + (size_t)(o0 + r) * Cc + kt + lc4 * 4);
        }
    };

    prefetch(0, 0);
    CP_COMMIT();

    for (int kt8 = 0; kt8 < 8; kt8++) {
        if (kt8 < 7) { prefetch(kt8 + 1, (kt8 + 1) & 1); CP_COMMIT(); CP_WAIT1(); }
        else CP_WAIT0();
        __syncthreads();
        const uint32_t* Asu = (const uint32_t*)(dsm + (kt8 & 1) * STAGEF);
        const uint32_t* Wsu = Asu + 4608;
        #pragma unroll
        for (int ks = 0; ks < 4; ks++) {
            const int k = ks * 8;
            const int ar = wm * 64 + (l >> 2);
            const int ac = k + (l & 3);
            uint32_t a[4][4];
            #pragma unroll
            for (int mf = 0; mf < 4; mf++) {
                const int r0 = (ar + mf * 16) * ASTRIDE;
                a[mf][0] = Asu[r0 + ac];
                a[mf][1] = Asu[r0 + 8 * ASTRIDE + ac];
                a[mf][2] = Asu[r0 + ac + 4];
                a[mf][3] = Asu[r0 + 8 * ASTRIDE + ac + 4];
            }
            uint32_t bf[4][2];
            const int bn = wn * 32 + (l >> 2);
            #pragma unroll
            for (int nf = 0; nf < 4; nf++) {
                const int r0 = (bn + nf * 8) * ASTRIDE;
                bf[nf][0] = Wsu[r0 + ac];
                bf[nf][1] = Wsu[r0 + ac + 4];
            }
            #pragma unroll
            for (int mf = 0; mf < 4; mf++)
                #pragma unroll
                for (int nf = 0; nf < 4; nf++)
                    mma_tf32(c[mf][nf], a[mf][0], a[mf][1], a[mf][2], a[mf][3],
                             bf[nf][0], bf[nf][1]);
        }
        __syncthreads();
    }

    if (MODE == 0 && o0 < 256) {
        // q blocks: direct fragment store to g_qt[b][n][o], bias + elu+1
        float* Qt = g_qt + (size_t)b * Nn * Cc;
        #pragma unroll
        for (int mf = 0; mf < 4; mf++) {
            const int rn = n0 + wm * 64 + mf * 16 + (l >> 2);
            #pragma unroll
            for (int nf = 0; nf < 4; nf++) {
                const int col = o0 + wn * 32 + nf * 8 + (l & 3) * 2;
                const float b0 = __ldg(bias + col);
                const float b1 = __ldg(bias + col + 1);
                float v0 = c[mf][nf][0] + b0, v1 = c[mf][nf][1] + b1;
                float v2 = c[mf][nf][2] + b0, v3 = c[mf][nf][3] + b1;
                v0 = v0 > 0.f ? v0 + 1.f : expf(v0);
                v1 = v1 > 0.f ? v1 + 1.f : expf(v1);
                v2 = v2 > 0.f ? v2 + 1.f : expf(v2);
                v3 = v3 > 0.f ? v3 + 1.f : expf(v3);
                *(float2*)(Qt + (size_t)rn * Cc + col)       = make_float2(v0, v1);
                *(float2*)(Qt + (size_t)(rn + 8) * Cc + col) = make_float2(v2, v3);
            }
        }
        return;
    }

    // transpose epilogue through smem (Cs overlays stage 0)
    float* const Cs = dsm;
    #pragma unroll
    for (int half = 0; half < 2; half++) {
        if (wm == half) {
            #pragma unroll
            for (int mf = 0; mf < 4; mf++) {
                const int row = mf * 16 + (l >> 2);
                #pragma unroll
                for (int nf = 0; nf < 4; nf++) {
                    const int col = wn * 32 + nf * 8 + (l & 3) * 2;
                    Cs[row * CSTRIDE + col]           = c[mf][nf][0];
                    Cs[row * CSTRIDE + col + 1]       = c[mf][nf][1];
                    Cs[(row + 8) * CSTRIDE + col]     = c[mf][nf][2];
                    Cs[(row + 8) * CSTRIDE + col + 1] = c[mf][nf][3];
                }
            }
        }
        __syncthreads();
        const int nl = t & 63;
        const int ol0 = t >> 6;
        const int n = n0 + half * 64 + nl;
        #pragma unroll
        for (int j = 0; j < 32; j++) {
            const int o = ol0 + j * 4;
            const int og = o0 + o;
            float v = Cs[nl * CSTRIDE + o] + __ldg(bias + og);
            if (MODE == 0) {
                if (og < 2 * Cc) v = v > 0.f ? v + 1.f : expf(v);  // k rows
                g_qkv[((size_t)b * THREEC + og) * Nn + n] = v;
            } else {
                v += __ldg(resid + ((size_t)b * Cc + og) * Nn + n);
                Yout[((size_t)b * Cc + og) * Nn + n] = v;
            }
        }
        __syncthreads();
    }
}

// ============================================================
// K3: kvT[e,d] = sum_n v[e,n] k[d,n] via tf32 mma. Per (bh, split of 1024 n).
// Also ks[d] = sum_n k[d,n]. cp.async double-buffered, BK(n)=32.
// ============================================================
__global__ __launch_bounds__(256) void kv_mma() {
    __shared__ __align__(16) float sm[2 * 2 * 64 * ASTRIDE];  // [stage][V|K][64][36]
    __shared__ float red[128];
    const int bh = blockIdx.x, sp = blockIdx.y;
    const int b = bh >> 2, h = bh & 3;
    const float* Vp = g_qkv + ((size_t)b * THREEC + 2 * Cc + h * 64) * Nn;
    const float* Kp = g_qkv + ((size_t)b * THREEC + Cc + h * 64) * Nn;
    const int t = threadIdx.x, l = t & 31, wid = t >> 5;
    const int wm = wid & 1, wn = wid >> 1;
    const uint32_t sb = smem_u32(sm);
    const int nbase = sp * 1024;

    float c[2][2][4] = {};
    float ksp = 0.f;

    auto prefetch = [&](int nt, int stg) {
        #pragma unroll
        for (int q = 0; q < 2; q++) {
            const int f = t + q * 256;
            const int r = f >> 3, c4 = f & 7;
            const uint32_t off = (uint32_t)(stg * 4608 + r * ASTRIDE + c4 * 4) * 4;
            CP16(sb + off,            Vp + (size_t)r * Nn + nbase + nt * 32 + c4 * 4);
            CP16(sb + off + 2304 * 4, Kp + (size_t)r * Nn + nbase + nt * 32 + c4 * 4);
        }
    };

    prefetch(0, 0);
    CP_COMMIT();

    for (int nt = 0; nt < 32; nt++) {
        if (nt < 31) { prefetch(nt + 1, (nt + 1) & 1); CP_COMMIT(); CP_WAIT1(); }
        else CP_WAIT0();
        __syncthreads();
        const float* Vs = sm + (nt & 1) * 4608;
        const float* Ks = Vs + 2304;
        const uint32_t* Vsu = (const uint32_t*)Vs;
        const uint32_t* Ksu = (const uint32_t*)Ks;
        #pragma unroll
        for (int ks8 = 0; ks8 < 4; ks8++) {
            const int k = ks8 * 8;
            const int ar = wm * 32 + (l >> 2);
            const int ac = k + (l & 3);
            uint32_t a[2][4];
            #pragma unroll
            for (int mf = 0; mf < 2; mf++) {
                const int r0 = (ar + mf * 16) * ASTRIDE;
                a[mf][0] = Vsu[r0 + ac];
                a[mf][1] = Vsu[r0 + 8 * ASTRIDE + ac];
                a[mf][2] = Vsu[r0 + ac + 4];
                a[mf][3] = Vsu[r0 + 8 * ASTRIDE + ac + 4];
            }
            uint32_t bf[2][2];
            const int bn = wn * 16 + (l >> 2);
            #pragma unroll
            for (int nf = 0; nf < 2; nf++) {
                const int r0 = (bn + nf * 8) * ASTRIDE;
                bf[nf][0] = Ksu[r0 + ac];
                bf[nf][1] = Ksu[r0 + ac + 4];
            }
            #pragma unroll
            for (int mf = 0; mf < 2; mf++)
                #pragma unroll
                for (int nf = 0; nf < 2; nf++)
                    mma_tf32(c[mf][nf], a[mf][0], a[mf][1], a[mf][2], a[mf][3],
                             bf[nf][0], bf[nf][1]);
        }
        if (t < 128) {
            const int row = t & 63, hf = t >> 6;
            #pragma unroll
            for (int j = 0; j < 16; j++) ksp += Ks[row * ASTRIDE + hf * 16 + j];
        }
        __syncthreads();
    }

    if (t < 128) red[t] = ksp;
    __syncthreads();
    if (t < 64) g_ks[((size_t)sp * 64 + bh) * 64 + t] = red[t] + red[t + 64];

    float* kvout = g_kv + ((size_t)sp * 64 + bh) * 4096;
    #pragma unroll
    for (int mf = 0; mf < 2; mf++) {
        const int re = wm * 32 + mf * 16 + (l >> 2);
        #pragma unroll
        for (int nf = 0; nf < 2; nf++) {
            const int cd = wn * 16 + nf * 8 + (l & 3) * 2;
            *(float2*)(kvout + (size_t)re * 64 + cd)       = make_float2(c[mf][nf][0], c[mf][nf][1]);
            *(float2*)(kvout + (size_t)(re + 8) * 64 + cd) = make_float2(c[mf][nf][2], c[mf][nf][3]);
        }
    }
}

// ============================================================
// K3b: reduce kv/ks splits into slot 0. grid (64 bh, 4 quarters)
// ============================================================
__global__ __launch_bounds__(256) void kvreduce_kernel() {
    const int bh = blockIdx.x, cq = blockIdx.y;
    const int t = threadIdx.x;
    const int i = cq * 1024 + t * 4;
    float4 s = make_float4(0.f, 0.f, 0.f, 0.f);
    #pragma unroll
    for (int sp = 0; sp < NSPLIT; sp++) {
        const float4 v = *(const float4*)(g_kv + ((size_t)sp * 64 + bh) * 4096 + i);
        s.x += v.x; s.y += v.y; s.z += v.z; s.w += v.w;
    }
    *(float4*)(g_kv + (size_t)bh * 4096 + i) = s;
    if (cq == 0 && t < 64) {
        float ks = 0.f;
        #pragma unroll
        for (int sp = 0; sp < NSPLIT; sp++)
            ks += g_ks[((size_t)sp * 64 + bh) * 64 + t];
        g_ks[(size_t)bh * 64 + t] = ks;
    }
}

// ============================================================
// K4: out[e,n] = (sum_d kvT[e,d] q[d,n]) / (q·ks + eps) via tf32 mma.
// grid (bh, 64 n-tiles of 64). Writes g_attnt[b][n][h*64+e].
// ============================================================
__global__ __launch_bounds__(256) void attn_mma() {
    __shared__ __align__(16) float kvs[64 * 68];
    __shared__ __align__(16) float qs[64 * 68];   // reused as transpose buffer
    __shared__ float kss[64], sden[64];
    const int bh = blockIdx.x, b = bh >> 2, h = bh & 3;
    const int n0 = blockIdx.y * 64;
    const int t = threadIdx.x, l = t & 31, wid = t >> 5;
    const int wm = wid & 1, wn = wid >> 1;

    for (int i = t; i < 4096; i += 256)
        kvs[(i >> 6) * 68 + (i & 63)] = g_kv[(size_t)bh * 4096 + i];
    if (t < 64) kss[t] = g_ks[(size_t)bh * 64 + t];
    const float* Qt = g_qt + ((size_t)b * Nn + n0) * Cc + h * 64;
    for (int f = t; f < 1024; f += 256) {
        const int r = f >> 4, c4 = f & 15;
        *(float4*)&qs[r * 68 + c4 * 4] = *(const float4*)(Qt + (size_t)r * Cc + c4 * 4);
    }
    __syncthreads();
    if (t < 64) {
        float den = 0.f;
        #pragma unroll
        for (int d = 0; d < 64; d++) den += qs[t * 68 + d] * kss[d];
        sden[t] = 1.f / (den + 1e-6f);
    }
    __syncthreads();

    float c[2][2][4] = {};
    const uint32_t* Au = (const uint32_t*)kvs;
    const uint32_t* Bu = (const uint32_t*)qs;
    #pragma unroll
    for (int ks8 = 0; ks8 < 8; ks8++) {
        const int k = ks8 * 8;
        const int ar = wm * 32 + (l >> 2);
        const int ac = k + (l & 3);
        uint32_t a[2][4];
        #pragma unroll
        for (int mf = 0; mf < 2; mf++) {
            const int r0 = (ar + mf * 16) * 68;
            a[mf][0] = Au[r0 + ac];
            a[mf][1] = Au[r0 + 8 * 68 + ac];
            a[mf][2] = Au[r0 + ac + 4];
            a[mf][3] = Au[r0 + 8 * 68 + ac + 4];
        }
        uint32_t bf[2][2];
        const int bn = wn * 16 + (l >> 2);
        #pragma unroll
        for (int nf = 0; nf < 2; nf++) {
            const int r0 = (bn + nf * 8) * 68;
            bf[nf][0] = Bu[r0 + ac];
            bf[nf][1] = Bu[r0 + ac + 4];
        }
        #pragma unroll
        for (int mf = 0; mf < 2; mf++)
            #pragma unroll
            for (int nf = 0; nf < 2; nf++)
                mma_tf32(c[mf][nf], a[mf][0], a[mf][1], a[mf][2], a[mf][3],
                         bf[nf][0], bf[nf][1]);
    }
    __syncthreads();   // all reads of qs done; reuse as Cs[n][e]

    #pragma unroll
    for (int mf = 0; mf < 2; mf++) {
        const int re = wm * 32 + mf * 16 + (l >> 2);
        #pragma unroll
        for (int nf = 0; nf < 2; nf++) {
            const int cn = wn * 16 + nf * 8 + (l & 3) * 2;
            const float s0 = sden[cn], s1 = sden[cn + 1];
            qs[cn * 68 + re]           = c[mf][nf][0] * s0;
            qs[(cn + 1) * 68 + re]     = c[mf][nf][1] * s1;
            qs[cn * 68 + re + 8]       = c[mf][nf][2] * s0;
            qs[(cn + 1) * 68 + re + 8] = c[mf][nf][3] * s1;
        }
    }
    __syncthreads();

    float* Op = g_attnt + ((size_t)b * Nn + n0) * Cc + h * 64;
    #pragma unroll
    for (int p = 0; p < 4; p++) {
        const int n = (t >> 4) + p * 16;
        const int e4 = t & 15;
        *(float4*)(Op + (size_t)n * Cc + e4 * 4) = *(const float4*)&qs[n * 68 + e4 * 4];
    }
}

// ============================================================
extern "C" void kernel_launch(void* const* d_in, const int* in_sizes, int n_in,
                              void* d_out, int out_size) {
    const float* x     = (const float*)d_in[0];
    const float* gamma = (const float*)d_in[1];
    const float* beta  = (const float*)d_in[2];
    const float* w_qkv = (const float*)d_in[3];
    const float* b_qkv = (const float*)d_in[4];
    const float* w_out = (const float*)d_in[5];
    const float* b_out = (const float*)d_in[6];
    float* out = (float*)d_out;

    const int dyn = STAGEF * 2 * 4;  // 73728 B
    cudaFuncSetAttribute(mma_gemm<0>, cudaFuncAttributeMaxDynamicSharedMemorySize, dyn);
    cudaFuncSetAttribute(mma_gemm<1>, cudaFuncAttributeMaxDynamicSharedMemorySize, dyn);

    gn_kernel<<<Bb * 32, 256>>>(x, gamma, beta);

    dim3 g2(Nn / 128, THREEC / 128, Bb);
    mma_gemm<0><<<g2, 256, dyn>>>(w_qkv, b_qkv, nullptr, nullptr);

    dim3 g3(Bb * Hh, NSPLIT);
    kv_mma<<<g3, 256>>>();

    dim3 g3b(Bb * Hh, 4);
    kvreduce_kernel<<<g3b, 256>>>();

    dim3 g4(Bb * Hh, Nn / 64);
    attn_mma<<<g4, 256>>>();

    dim3 g5(Nn / 128, Cc / 128, Bb);
    mma_gemm<1><<<g5, 256, dyn>>>(w_out, b_out, x, out);
}